// round 12
// baseline (speedup 1.0000x reference)
#include <cuda_runtime.h>
#include <cuda_fp16.h>
#include <cuda_bf16.h>
#include <cstdint>

constexpr int N_NODES = 50000;
constexpr int N_EDGES = 1600000;
constexpr int IN_DIM  = 256;
constexpr int HD      = 128;   // HEADS * OUT_DIM

constexpr int SCAN_BLK  = 1024;
constexpr int SCAN_NBLK = (N_NODES + SCAN_BLK - 1) / SCAN_BLK;   // 49

constexpr int TILE_M = 64;                 // 2 CTAs/SM
constexpr int KC     = 32;                 // bf16 K-chunk
constexpr int KPAD   = 40;                 // smem row stride (conflict-free)
constexpr int NCH    = IN_DIM / KC;        // 8 chunks

// ---------------- scratch (static device globals) ----------------------------
__device__ uint4  g_hh[N_NODES * (HD / 8)];  // h fp16 packed (12.8 MB)
__device__ __nv_bfloat16 g_WH[HD * IN_DIM];  // W hi bf16 (64 KB, pre-split)
__device__ __nv_bfloat16 g_WL[HD * IN_DIM];  // W lo bf16 (64 KB, pre-split)
__device__ float4 g_ssrc[N_NODES];           // per-node src scores (atomic-built)
__device__ float4 g_sdst[N_NODES];
__device__ float4 g_csr_ex[N_EDGES];
__device__ int    g_csr_src[N_EDGES];
__device__ int    g_count[N_NODES];
__device__ int    g_start[N_NODES + 1];
__device__ int    g_cursor[N_NODES];
__device__ int    g_blocksum[SCAN_NBLK];

// ---------------- helpers ----------------------------------------------------
__device__ __forceinline__ unsigned pack_h2(float a, float b) {   // fp16 pair
    __half2 h = __float22half2_rn(make_float2(a, b));
    return *reinterpret_cast<unsigned*>(&h);
}
__device__ __forceinline__ float2 unpack_h2(unsigned u) {
    __half2 h = *reinterpret_cast<__half2*>(&u);
    return __half22float2(h);
}
__device__ __forceinline__ unsigned pack_bf2(__nv_bfloat16 a, __nv_bfloat16 b) {
    __nv_bfloat162 t = __halves2bfloat162(a, b);
    return *reinterpret_cast<unsigned*>(&t);
}
__device__ __forceinline__ uint32_t ld2(const uint16_t* p) {
    return *reinterpret_cast<const uint32_t*>(p);
}
// HMMA bf16: m16n8k16, row.col, fp32 accumulate (baseline PTX, sm_80+)
__device__ __forceinline__ void mma16816(float* d, const uint32_t* a,
                                         uint32_t b0, uint32_t b1) {
    asm volatile(
        "mma.sync.aligned.m16n8k16.row.col.f32.bf16.bf16.f32 "
        "{%0,%1,%2,%3}, {%4,%5,%6,%7}, {%8,%9}, {%0,%1,%2,%3};"
        : "+f"(d[0]), "+f"(d[1]), "+f"(d[2]), "+f"(d[3])
        : "r"(a[0]), "r"(a[1]), "r"(a[2]), "r"(a[3]), "r"(b0), "r"(b1));
}
// split fp32 -> (hi, lo) bf16 pair packs for 4 consecutive values
__device__ __forceinline__ void split4(float4 v, uint2& hi, uint2& lo) {
    __nv_bfloat16 h0 = __float2bfloat16_rn(v.x);
    __nv_bfloat16 h1 = __float2bfloat16_rn(v.y);
    __nv_bfloat16 h2 = __float2bfloat16_rn(v.z);
    __nv_bfloat16 h3 = __float2bfloat16_rn(v.w);
    hi = make_uint2(pack_bf2(h0, h1), pack_bf2(h2, h3));
    lo = make_uint2(pack_bf2(__float2bfloat16_rn(v.x - __bfloat162float(h0)),
                             __float2bfloat16_rn(v.y - __bfloat162float(h1))),
                    pack_bf2(__float2bfloat16_rn(v.z - __bfloat162float(h2)),
                             __float2bfloat16_rn(v.w - __bfloat162float(h3))));
}

// ---------------- 0. zero counters + score accumulators ----------------------
__global__ __launch_bounds__(SCAN_BLK) void zero_kernel() {
    int n = blockIdx.x * SCAN_BLK + threadIdx.x;
    if (n < N_NODES) {
        g_count[n] = 0;
        g_ssrc[n] = make_float4(0.f, 0.f, 0.f, 0.f);
        g_sdst[n] = make_float4(0.f, 0.f, 0.f, 0.f);
    }
}

// ---------------- 0b. one-time W split: fp32 -> bf16 hi/lo -------------------
__global__ __launch_bounds__(256) void wsplit_kernel(const float* __restrict__ W) {
    int i = blockIdx.x * 256 + threadIdx.x;          // float4 slot
    if (i >= HD * IN_DIM / 4) return;
    float4 v = *reinterpret_cast<const float4*>(&W[i * 4]);
    uint2 hi, lo;
    split4(v, hi, lo);
    *reinterpret_cast<uint2*>(&g_WH[i * 4]) = hi;
    *reinterpret_cast<uint2*>(&g_WL[i * 4]) = lo;
}

// ---------------- 1. in-degree histogram -------------------------------------
__global__ __launch_bounds__(256) void count_kernel(const int* __restrict__ idx) {
    int e = blockIdx.x * blockDim.x + threadIdx.x;
    if (e >= N_EDGES) return;
    int2 p = reinterpret_cast<const int2*>(idx)[e];
    atomicAdd(&g_count[p.y], 1);
}

// ---------------- 2. hierarchical prefix sum ---------------------------------
__global__ __launch_bounds__(SCAN_BLK) void scan_blocks_kernel() {
    __shared__ int sh[SCAN_BLK];
    int tid = threadIdx.x;
    int n = blockIdx.x * SCAN_BLK + tid;
    int v = (n < N_NODES) ? g_count[n] : 0;
    sh[tid] = v;
    __syncthreads();
#pragma unroll
    for (int off = 1; off < SCAN_BLK; off <<= 1) {
        int t = (tid >= off) ? sh[tid - off] : 0;
        __syncthreads();
        sh[tid] += t;
        __syncthreads();
    }
    if (n < N_NODES) g_start[n] = sh[tid] - v;
    if (tid == SCAN_BLK - 1) g_blocksum[blockIdx.x] = sh[tid];
}
__global__ __launch_bounds__(64) void scan_tops_kernel() {
    __shared__ int sh[64];
    int tid = threadIdx.x;
    int v = (tid < SCAN_NBLK) ? g_blocksum[tid] : 0;
    sh[tid] = v;
    __syncthreads();
#pragma unroll
    for (int off = 1; off < 64; off <<= 1) {
        int t = (tid >= off) ? sh[tid - off] : 0;
        __syncthreads();
        sh[tid] += t;
        __syncthreads();
    }
    if (tid < SCAN_NBLK) g_blocksum[tid] = sh[tid] - v;
}
__global__ __launch_bounds__(SCAN_BLK) void scan_apply_kernel() {
    int n = blockIdx.x * SCAN_BLK + threadIdx.x;
    if (n >= N_NODES) return;
    int s = g_start[n] + g_blocksum[blockIdx.x];
    g_start[n]  = s;
    g_cursor[n] = s;
    if (n == 0) g_start[N_NODES] = N_EDGES;
}

// ---------------- 3. pipelined HMMA GEMM + fused scores ----------------------
// h = x_hi*W_hi + x_hi*W_lo + x_lo*W_hi (fp32 acc). W comes pre-split in bf16.
// Epilogue: packed fp16 h + per-node attention scores via fp32 atomics.
__global__ __launch_bounds__(256, 2) void gemm_fused_kernel(
        const float* __restrict__ x,
        const float* __restrict__ a_src, const float* __restrict__ a_dst) {
    __shared__ uint16_t XH[2][TILE_M][KPAD];
    __shared__ uint16_t XL[2][TILE_M][KPAD];
    __shared__ uint16_t WH[2][HD][KPAD];
    __shared__ uint16_t WL[2][HD][KPAD];

    const int tid  = threadIdx.x;
    const int lane = tid & 31;
    const int wid  = tid >> 5;
    const int warp_m = wid >> 1;        // 0..3 -> rows 16*warp_m
    const int warp_n = wid & 1;         // 0..1 -> cols 64*warp_n
    const int mBase = blockIdx.x * TILE_M;

    const int qr = lane >> 2;           // 0..7
    const int qc = (lane & 3) * 2;      // 0,2,4,6

    // x load map: 64 rows x 8 float4 (512 slots, 2/thread)
    const int xr0 = tid >> 3,         xc0 = (tid & 7) * 4;
    const int xr1 = (256 + tid) >> 3, xc1 = ((256 + tid) & 7) * 4;
    // W load map (bf16 uint4 = 8 elems): 128 rows x 4 groups (512 slots, 2/thread)
    const int wr0 = tid >> 2,         wc0 = (tid & 3) * 8;
    const int wr1 = (256 + tid) >> 2, wc1 = ((256 + tid) & 3) * 8;

    float d[8][4];
#pragma unroll
    for (int j = 0; j < 8; j++)
#pragma unroll
        for (int t = 0; t < 4; t++) d[j][t] = 0.f;

    float4 xv[2];
    uint4 whi[2], wlo[2];
    const bool xok0 = (mBase + xr0 < N_NODES);
    const bool xok1 = (mBase + xr1 < N_NODES);
    // prologue: chunk 0
    xv[0] = xok0 ? *reinterpret_cast<const float4*>(&x[(long)(mBase + xr0) * IN_DIM + xc0])
                 : make_float4(0.f, 0.f, 0.f, 0.f);
    xv[1] = xok1 ? *reinterpret_cast<const float4*>(&x[(long)(mBase + xr1) * IN_DIM + xc1])
                 : make_float4(0.f, 0.f, 0.f, 0.f);
    whi[0] = *reinterpret_cast<const uint4*>(&g_WH[wr0 * IN_DIM + wc0]);
    wlo[0] = *reinterpret_cast<const uint4*>(&g_WL[wr0 * IN_DIM + wc0]);
    whi[1] = *reinterpret_cast<const uint4*>(&g_WH[wr1 * IN_DIM + wc1]);
    wlo[1] = *reinterpret_cast<const uint4*>(&g_WL[wr1 * IN_DIM + wc1]);

    for (int c = 0; c < NCH; c++) {
        const int b = c & 1;
        // ---- stage prefetched regs -> smem buffer b ----
        {
            uint2 hi, lo;
            split4(xv[0], hi, lo);
            *reinterpret_cast<uint2*>(&XH[b][xr0][xc0]) = hi;
            *reinterpret_cast<uint2*>(&XL[b][xr0][xc0]) = lo;
            split4(xv[1], hi, lo);
            *reinterpret_cast<uint2*>(&XH[b][xr1][xc1]) = hi;
            *reinterpret_cast<uint2*>(&XL[b][xr1][xc1]) = lo;
            *reinterpret_cast<uint4*>(&WH[b][wr0][wc0]) = whi[0];
            *reinterpret_cast<uint4*>(&WL[b][wr0][wc0]) = wlo[0];
            *reinterpret_cast<uint4*>(&WH[b][wr1][wc1]) = whi[1];
            *reinterpret_cast<uint4*>(&WL[b][wr1][wc1]) = wlo[1];
        }
        __syncthreads();

        // ---- issue LDGs for chunk c+1 (overlap with MMA below) ----
        if (c + 1 < NCH) {
            const int k0 = (c + 1) * KC;
            xv[0] = xok0 ? *reinterpret_cast<const float4*>(&x[(long)(mBase + xr0) * IN_DIM + k0 + xc0])
                         : make_float4(0.f, 0.f, 0.f, 0.f);
            xv[1] = xok1 ? *reinterpret_cast<const float4*>(&x[(long)(mBase + xr1) * IN_DIM + k0 + xc1])
                         : make_float4(0.f, 0.f, 0.f, 0.f);
            whi[0] = *reinterpret_cast<const uint4*>(&g_WH[wr0 * IN_DIM + k0 + wc0]);
            wlo[0] = *reinterpret_cast<const uint4*>(&g_WL[wr0 * IN_DIM + k0 + wc0]);
            whi[1] = *reinterpret_cast<const uint4*>(&g_WH[wr1 * IN_DIM + k0 + wc1]);
            wlo[1] = *reinterpret_cast<const uint4*>(&g_WL[wr1 * IN_DIM + k0 + wc1]);
        }

        // ---- MMA from buffer b ----
#pragma unroll
        for (int ks = 0; ks < 2; ks++) {
            const int kb = ks * 16 + qc;
            const int r = warp_m * 16 + qr;
            uint32_t a[4];
            a[0] = ld2(&XH[b][r][kb]);     a[1] = ld2(&XH[b][r + 8][kb]);
            a[2] = ld2(&XH[b][r][kb + 8]); a[3] = ld2(&XH[b][r + 8][kb + 8]);
#pragma unroll
            for (int j = 0; j < 8; j++) {
                int n = warp_n * 64 + j * 8 + qr;
                uint32_t b0 = ld2(&WH[b][n][kb]), b1 = ld2(&WH[b][n][kb + 8]);
                mma16816(d[j], a, b0, b1);
                uint32_t c0 = ld2(&WL[b][n][kb]), c1 = ld2(&WL[b][n][kb + 8]);
                mma16816(d[j], a, c0, c1);
            }
            a[0] = ld2(&XL[b][r][kb]);     a[1] = ld2(&XL[b][r + 8][kb]);
            a[2] = ld2(&XL[b][r][kb + 8]); a[3] = ld2(&XL[b][r + 8][kb + 8]);
#pragma unroll
            for (int j = 0; j < 8; j++) {
                int n = warp_n * 64 + j * 8 + qr;
                uint32_t b0 = ld2(&WH[b][n][kb]), b1 = ld2(&WH[b][n][kb + 8]);
                mma16816(d[j], a, b0, b1);
            }
        }
        // single barrier/iter: next STS hits the other buffer.
    }

    // ---- epilogue: packed fp16 h + fused attention scores ----
    unsigned* hhu = reinterpret_cast<unsigned*>(g_hh);
    float* ssrcf = reinterpret_cast<float*>(g_ssrc);
    float* sdstf = reinterpret_cast<float*>(g_sdst);

    const int node0 = mBase + warp_m * 16 + qr;
    const int node1 = node0 + 8;

    float ps0[2] = {0.f, 0.f}, pd0[2] = {0.f, 0.f};
    float ps1[2] = {0.f, 0.f}, pd1[2] = {0.f, 0.f};
#pragma unroll
    for (int j = 0; j < 8; j++) {
        int colb = warp_n * 64 + j * 8 + qc;          // even; pair stays in head
        int hl   = (j * 8 + qc) >> 5;                 // 0/1 within warp's heads
        int head = warp_n * 2 + hl;
#pragma unroll
        for (int t = 0; t < 2; t++) {
            int dim = (colb + t) & 31;
            float asv = __ldg(&a_src[head * 32 + dim]);
            float adv = __ldg(&a_dst[head * 32 + dim]);
            ps0[hl] += d[j][t] * asv;     pd0[hl] += d[j][t] * adv;
            ps1[hl] += d[j][2 + t] * asv; pd1[hl] += d[j][2 + t] * adv;
        }
        if (node0 < N_NODES)
            hhu[node0 * 64 + (colb >> 1)] = pack_h2(d[j][0], d[j][1]);
        if (node1 < N_NODES)
            hhu[node1 * 64 + (colb >> 1)] = pack_h2(d[j][2], d[j][3]);
    }
#pragma unroll
    for (int hl = 0; hl < 2; hl++) {
        int head = warp_n * 2 + hl;
        if (node0 < N_NODES) {
            atomicAdd(&ssrcf[node0 * 4 + head], ps0[hl]);
            atomicAdd(&sdstf[node0 * 4 + head], pd0[hl]);
        }
        if (node1 < N_NODES) {
            atomicAdd(&ssrcf[node1 * 4 + head], ps1[hl]);
            atomicAdd(&sdstf[node1 * 4 + head], pd1[hl]);
        }
    }
}

// ---------------- 5. edge scatter: ex + CSR placement ------------------------
// Softmax is shift-invariant and e = tanh(.)*w in (-1,1) is bounded, so the
// reference's segment_max subtraction is mathematically a no-op.
__global__ __launch_bounds__(256) void scatter_kernel(const int* __restrict__ idx,
                                                      const float* __restrict__ wts) {
    int e = blockIdx.x * blockDim.x + threadIdx.x;
    if (e >= N_EDGES) return;
    int2 p = reinterpret_cast<const int2*>(idx)[e];
    int s = p.x, d = p.y;
    float w = wts[e];
    float4 a = g_ssrc[s];
    float4 b = g_sdst[d];
    float4 ex;
    ex.x = __expf(tanhf(a.x + b.x) * w);
    ex.y = __expf(tanhf(a.y + b.y) * w);
    ex.z = __expf(tanhf(a.z + b.z) * w);
    ex.w = __expf(tanhf(a.w + b.w) * w);
    int pos = atomicAdd(&g_cursor[d], 1);
    g_csr_ex[pos]  = ex;
    g_csr_src[pos] = s;
}

// ---------------- 6. single-pass aggregation + fused GELU (warp per dst) -----
// out = (sum_e ex_e * h_src) / (sum_e ex_e)  — denom fused into gather loop.
__global__ __launch_bounds__(256) void aggregate_kernel(float* __restrict__ out) {
    int d = (blockIdx.x * blockDim.x + threadIdx.x) >> 5;
    if (d >= N_NODES) return;
    int lane = threadIdx.x & 31;
    int h2 = lane >> 3;                 // head owning my out cols

    int start = g_start[d];
    int end   = g_start[d + 1];

    const float* exf = reinterpret_cast<const float*>(g_csr_ex);
    const uint2* hh2 = reinterpret_cast<const uint2*>(g_hh);

    float dsum = 0.f;
    float4 acc = make_float4(0.f, 0.f, 0.f, 0.f);
#pragma unroll 4
    for (int e = start; e < end; e++) {
        int src = __ldg(&g_csr_src[e]);          // warp-uniform broadcast
        float exv = __ldg(&exf[e * 4 + h2]);
        uint2 raw = __ldg(&hh2[src * 32 + lane]);
        dsum += exv;
        float2 f01 = unpack_h2(raw.x);
        float2 f23 = unpack_h2(raw.y);
        acc.x += exv * f01.x; acc.y += exv * f01.y;
        acc.z += exv * f23.x; acc.w += exv * f23.y;
    }
    float inv = (end > start) ? 1.f / dsum : 0.f;   // deg==0 -> out 0 (= ref)

    const float r = 0.70710678118654752f;
    float4 v;
    acc.x *= inv; acc.y *= inv; acc.z *= inv; acc.w *= inv;
    v.x = 0.5f * acc.x * (1.f + erff(acc.x * r));
    v.y = 0.5f * acc.y * (1.f + erff(acc.y * r));
    v.z = 0.5f * acc.z * (1.f + erff(acc.z * r));
    v.w = 0.5f * acc.w * (1.f + erff(acc.w * r));
    reinterpret_cast<float4*>(out)[d * 32 + lane] = v;
}

// ---------------- launch -----------------------------------------------------
extern "C" void kernel_launch(void* const* d_in, const int* in_sizes, int n_in,
                              void* d_out, int out_size) {
    const float* x     = (const float*)d_in[0];
    const int*   idx   = (const int*)d_in[1];     // int64 stored as int32 pairs
    const float* wts   = (const float*)d_in[2];
    const float* W     = (const float*)d_in[3];
    const float* a_src = (const float*)d_in[4];
    const float* a_dst = (const float*)d_in[5];
    float* out = (float*)d_out;

    zero_kernel<<<SCAN_NBLK, SCAN_BLK>>>();                               // 1
    wsplit_kernel<<<(HD * IN_DIM / 4 + 255) / 256, 256>>>(W);             // 2
    count_kernel<<<(N_EDGES + 255) / 256, 256>>>(idx);                    // 3
    gemm_fused_kernel<<<(N_NODES + TILE_M - 1) / TILE_M, 256>>>(
        x, a_src, a_dst);                                                 // 4 <- profiled
    scan_blocks_kernel<<<SCAN_NBLK, SCAN_BLK>>>();                        // 5
    scan_tops_kernel<<<1, 64>>>();                                        // 6
    scan_apply_kernel<<<SCAN_NBLK, SCAN_BLK>>>();                         // 7
    scatter_kernel<<<(N_EDGES + 255) / 256, 256>>>(idx, wts);             // 8
    aggregate_kernel<<<(N_NODES * 32 + 255) / 256, 256>>>(out);           // 9
}

// round 13
// speedup vs baseline: 1.0292x; 1.0292x over previous
#include <cuda_runtime.h>
#include <cuda_fp16.h>
#include <cuda_bf16.h>
#include <cstdint>

constexpr int N_NODES = 50000;
constexpr int N_EDGES = 1600000;
constexpr int IN_DIM  = 256;
constexpr int HD      = 128;   // HEADS * OUT_DIM

constexpr int SCAN_BLK  = 1024;
constexpr int SCAN_NBLK = (N_NODES + SCAN_BLK - 1) / SCAN_BLK;   // 49

constexpr int TILE_M = 64;                 // 2 CTAs/SM
constexpr int KC     = 32;                 // bf16 K-chunk
constexpr int KPAD   = 40;                 // smem row stride (conflict-free)
constexpr int NCH    = IN_DIM / KC;        // 8 chunks

// ---------------- scratch (static device globals) ----------------------------
__device__ uint4  g_hh[N_NODES * (HD / 8)];  // h fp16 packed (12.8 MB)
__device__ float4 g_ssrc[N_NODES];           // per-node src scores (atomic-built)
__device__ float4 g_sdst[N_NODES];
__device__ float4 g_csr_ex[N_EDGES];
__device__ int    g_csr_src[N_EDGES];
__device__ int    g_count[N_NODES];
__device__ int    g_start[N_NODES + 1];
__device__ int    g_cursor[N_NODES];
__device__ int    g_blocksum[SCAN_NBLK];

// ---------------- helpers ----------------------------------------------------
__device__ __forceinline__ unsigned pack_h2(float a, float b) {   // fp16 pair
    __half2 h = __float22half2_rn(make_float2(a, b));
    return *reinterpret_cast<unsigned*>(&h);
}
__device__ __forceinline__ float2 unpack_h2(unsigned u) {
    __half2 h = *reinterpret_cast<__half2*>(&u);
    return __half22float2(h);
}
__device__ __forceinline__ unsigned pack_bf2(__nv_bfloat16 a, __nv_bfloat16 b) {
    __nv_bfloat162 t = __halves2bfloat162(a, b);
    return *reinterpret_cast<unsigned*>(&t);
}
__device__ __forceinline__ uint32_t ld2(const uint16_t* p) {
    return *reinterpret_cast<const uint32_t*>(p);
}
// HMMA bf16: m16n8k16, row.col, fp32 accumulate (baseline PTX, sm_80+)
__device__ __forceinline__ void mma16816(float* d, const uint32_t* a,
                                         uint32_t b0, uint32_t b1) {
    asm volatile(
        "mma.sync.aligned.m16n8k16.row.col.f32.bf16.bf16.f32 "
        "{%0,%1,%2,%3}, {%4,%5,%6,%7}, {%8,%9}, {%0,%1,%2,%3};"
        : "+f"(d[0]), "+f"(d[1]), "+f"(d[2]), "+f"(d[3])
        : "r"(a[0]), "r"(a[1]), "r"(a[2]), "r"(a[3]), "r"(b0), "r"(b1));
}
// split fp32 -> (hi, lo) bf16 pair packs for 4 consecutive values
__device__ __forceinline__ void split4(float4 v, uint2& hi, uint2& lo) {
    __nv_bfloat16 h0 = __float2bfloat16_rn(v.x);
    __nv_bfloat16 h1 = __float2bfloat16_rn(v.y);
    __nv_bfloat16 h2 = __float2bfloat16_rn(v.z);
    __nv_bfloat16 h3 = __float2bfloat16_rn(v.w);
    hi = make_uint2(pack_bf2(h0, h1), pack_bf2(h2, h3));
    lo = make_uint2(pack_bf2(__float2bfloat16_rn(v.x - __bfloat162float(h0)),
                             __float2bfloat16_rn(v.y - __bfloat162float(h1))),
                    pack_bf2(__float2bfloat16_rn(v.z - __bfloat162float(h2)),
                             __float2bfloat16_rn(v.w - __bfloat162float(h3))));
}

// ---------------- 0. zero counters + score accumulators ----------------------
__global__ __launch_bounds__(SCAN_BLK) void zero_kernel() {
    int n = blockIdx.x * SCAN_BLK + threadIdx.x;
    if (n < N_NODES) {
        g_count[n] = 0;
        g_ssrc[n] = make_float4(0.f, 0.f, 0.f, 0.f);
        g_sdst[n] = make_float4(0.f, 0.f, 0.f, 0.f);
    }
}

// ---------------- 1. in-degree histogram -------------------------------------
__global__ __launch_bounds__(256) void count_kernel(const int* __restrict__ idx) {
    int e = blockIdx.x * blockDim.x + threadIdx.x;
    if (e >= N_EDGES) return;
    int2 p = reinterpret_cast<const int2*>(idx)[e];
    atomicAdd(&g_count[p.y], 1);
}

// ---------------- 2. hierarchical prefix sum ---------------------------------
__global__ __launch_bounds__(SCAN_BLK) void scan_blocks_kernel() {
    __shared__ int sh[SCAN_BLK];
    int tid = threadIdx.x;
    int n = blockIdx.x * SCAN_BLK + tid;
    int v = (n < N_NODES) ? g_count[n] : 0;
    sh[tid] = v;
    __syncthreads();
#pragma unroll
    for (int off = 1; off < SCAN_BLK; off <<= 1) {
        int t = (tid >= off) ? sh[tid - off] : 0;
        __syncthreads();
        sh[tid] += t;
        __syncthreads();
    }
    if (n < N_NODES) g_start[n] = sh[tid] - v;
    if (tid == SCAN_BLK - 1) g_blocksum[blockIdx.x] = sh[tid];
}
__global__ __launch_bounds__(64) void scan_tops_kernel() {
    __shared__ int sh[64];
    int tid = threadIdx.x;
    int v = (tid < SCAN_NBLK) ? g_blocksum[tid] : 0;
    sh[tid] = v;
    __syncthreads();
#pragma unroll
    for (int off = 1; off < 64; off <<= 1) {
        int t = (tid >= off) ? sh[tid - off] : 0;
        __syncthreads();
        sh[tid] += t;
        __syncthreads();
    }
    if (tid < SCAN_NBLK) g_blocksum[tid] = sh[tid] - v;
}
__global__ __launch_bounds__(SCAN_BLK) void scan_apply_kernel() {
    int n = blockIdx.x * SCAN_BLK + threadIdx.x;
    if (n >= N_NODES) return;
    int s = g_start[n] + g_blocksum[blockIdx.x];
    g_start[n]  = s;
    g_cursor[n] = s;
    if (n == 0) g_start[N_NODES] = N_EDGES;
}

// ---------------- 3. pipelined HMMA GEMM + fused scores ----------------------
// h = x_hi*W_hi + x_hi*W_lo + x_lo*W_hi (fp32 acc). Epilogue: packed fp16 h
// AND per-node attention scores s_src/s_dst via fp32 atomics.
// Merged product loop: A_hi and A_lo held together so each WH fragment is
// loaded once per k-step (LDS per k-step 56 -> 40).
__global__ __launch_bounds__(256, 2) void gemm_fused_kernel(
        const float* __restrict__ x, const float* __restrict__ W,
        const float* __restrict__ a_src, const float* __restrict__ a_dst) {
    __shared__ uint16_t XH[2][TILE_M][KPAD];
    __shared__ uint16_t XL[2][TILE_M][KPAD];
    __shared__ uint16_t WH[2][HD][KPAD];
    __shared__ uint16_t WL[2][HD][KPAD];

    const int tid  = threadIdx.x;
    const int lane = tid & 31;
    const int wid  = tid >> 5;
    const int warp_m = wid >> 1;        // 0..3 -> rows 16*warp_m
    const int warp_n = wid & 1;         // 0..1 -> cols 64*warp_n
    const int mBase = blockIdx.x * TILE_M;

    const int qr = lane >> 2;           // 0..7
    const int qc = (lane & 3) * 2;      // 0,2,4,6

    // load maps: X = 64 rows x 8 float4 (512 slots, 2/thread),
    //            W = 128 rows x 8 float4 (1024 slots, 4/thread)
    const int xr0 = tid >> 3,         xc0 = (tid & 7) * 4;
    const int xr1 = (256 + tid) >> 3, xc1 = ((256 + tid) & 7) * 4;

    float d[8][4];
#pragma unroll
    for (int j = 0; j < 8; j++)
#pragma unroll
        for (int t = 0; t < 4; t++) d[j][t] = 0.f;

    float4 xv[2], wv[4];
    const bool xok0 = (mBase + xr0 < N_NODES);
    const bool xok1 = (mBase + xr1 < N_NODES);
    // prologue: chunk 0
    xv[0] = xok0 ? *reinterpret_cast<const float4*>(&x[(long)(mBase + xr0) * IN_DIM + xc0])
                 : make_float4(0.f, 0.f, 0.f, 0.f);
    xv[1] = xok1 ? *reinterpret_cast<const float4*>(&x[(long)(mBase + xr1) * IN_DIM + xc1])
                 : make_float4(0.f, 0.f, 0.f, 0.f);
#pragma unroll
    for (int q = 0; q < 4; q++) {
        int i = q * 256 + tid;
        wv[q] = *reinterpret_cast<const float4*>(&W[(long)(i >> 3) * IN_DIM + (i & 7) * 4]);
    }

    for (int c = 0; c < NCH; c++) {
        const int b = c & 1;
        // ---- convert prefetched regs -> smem buffer b ----
        {
            uint2 hi, lo;
            split4(xv[0], hi, lo);
            *reinterpret_cast<uint2*>(&XH[b][xr0][xc0]) = hi;
            *reinterpret_cast<uint2*>(&XL[b][xr0][xc0]) = lo;
            split4(xv[1], hi, lo);
            *reinterpret_cast<uint2*>(&XH[b][xr1][xc1]) = hi;
            *reinterpret_cast<uint2*>(&XL[b][xr1][xc1]) = lo;
#pragma unroll
            for (int q = 0; q < 4; q++) {
                int i = q * 256 + tid;
                split4(wv[q], hi, lo);
                *reinterpret_cast<uint2*>(&WH[b][i >> 3][(i & 7) * 4]) = hi;
                *reinterpret_cast<uint2*>(&WL[b][i >> 3][(i & 7) * 4]) = lo;
            }
        }
        __syncthreads();

        // ---- issue LDGs for chunk c+1 (overlap with MMA below) ----
        if (c + 1 < NCH) {
            const int k0 = (c + 1) * KC;
            xv[0] = xok0 ? *reinterpret_cast<const float4*>(&x[(long)(mBase + xr0) * IN_DIM + k0 + xc0])
                         : make_float4(0.f, 0.f, 0.f, 0.f);
            xv[1] = xok1 ? *reinterpret_cast<const float4*>(&x[(long)(mBase + xr1) * IN_DIM + k0 + xc1])
                         : make_float4(0.f, 0.f, 0.f, 0.f);
#pragma unroll
            for (int q = 0; q < 4; q++) {
                int i = q * 256 + tid;
                wv[q] = *reinterpret_cast<const float4*>(&W[(long)(i >> 3) * IN_DIM + k0 + (i & 7) * 4]);
            }
        }

        // ---- MMA from buffer b: merged 3-product loop ----
#pragma unroll
        for (int ks = 0; ks < 2; ks++) {
            const int kb = ks * 16 + qc;
            const int r = warp_m * 16 + qr;
            uint32_t ah[4], al[4];
            ah[0] = ld2(&XH[b][r][kb]);     ah[1] = ld2(&XH[b][r + 8][kb]);
            ah[2] = ld2(&XH[b][r][kb + 8]); ah[3] = ld2(&XH[b][r + 8][kb + 8]);
            al[0] = ld2(&XL[b][r][kb]);     al[1] = ld2(&XL[b][r + 8][kb]);
            al[2] = ld2(&XL[b][r][kb + 8]); al[3] = ld2(&XL[b][r + 8][kb + 8]);
#pragma unroll
            for (int j = 0; j < 8; j++) {
                int n = warp_n * 64 + j * 8 + qr;
                uint32_t b0 = ld2(&WH[b][n][kb]), b1 = ld2(&WH[b][n][kb + 8]);
                mma16816(d[j], ah, b0, b1);
                uint32_t c0 = ld2(&WL[b][n][kb]), c1 = ld2(&WL[b][n][kb + 8]);
                mma16816(d[j], ah, c0, c1);
                mma16816(d[j], al, b0, b1);     // WH frags reused from regs
            }
        }
        // single barrier/iter: next STS hits the other buffer.
    }

    // ---- epilogue: packed fp16 h + fused attention scores ----
    unsigned* hhu = reinterpret_cast<unsigned*>(g_hh);
    float* ssrcf = reinterpret_cast<float*>(g_ssrc);
    float* sdstf = reinterpret_cast<float*>(g_sdst);

    const int node0 = mBase + warp_m * 16 + qr;
    const int node1 = node0 + 8;

    // per-thread score partials: hl = j>>2 (qc-invariant), head = warp_n*2+hl
    float ps0[2] = {0.f, 0.f}, pd0[2] = {0.f, 0.f};
    float ps1[2] = {0.f, 0.f}, pd1[2] = {0.f, 0.f};
#pragma unroll
    for (int j = 0; j < 8; j++) {
        int colb = warp_n * 64 + j * 8 + qc;          // even; pair stays in head
        int hl   = j >> 2;                            // 0/1 within warp's heads
        int head = warp_n * 2 + hl;
#pragma unroll
        for (int t = 0; t < 2; t++) {
            int dim = (colb + t) & 31;
            float asv = __ldg(&a_src[head * 32 + dim]);
            float adv = __ldg(&a_dst[head * 32 + dim]);
            ps0[hl] += d[j][t] * asv;     pd0[hl] += d[j][t] * adv;
            ps1[hl] += d[j][2 + t] * asv; pd1[hl] += d[j][2 + t] * adv;
        }
        if (node0 < N_NODES)
            hhu[node0 * 64 + (colb >> 1)] = pack_h2(d[j][0], d[j][1]);
        if (node1 < N_NODES)
            hhu[node1 * 64 + (colb >> 1)] = pack_h2(d[j][2], d[j][3]);
    }
    // reduce across the 4 lanes sharing (node, head): lane = qr*4 + {0..3}
#pragma unroll
    for (int hl = 0; hl < 2; hl++) {
#pragma unroll
        for (int o = 1; o <= 2; o <<= 1) {
            ps0[hl] += __shfl_xor_sync(0xffffffffu, ps0[hl], o);
            pd0[hl] += __shfl_xor_sync(0xffffffffu, pd0[hl], o);
            ps1[hl] += __shfl_xor_sync(0xffffffffu, ps1[hl], o);
            pd1[hl] += __shfl_xor_sync(0xffffffffu, pd1[hl], o);
        }
    }
    if ((lane & 3) == 0) {
#pragma unroll
        for (int hl = 0; hl < 2; hl++) {
            int head = warp_n * 2 + hl;
            if (node0 < N_NODES) {
                atomicAdd(&ssrcf[node0 * 4 + head], ps0[hl]);
                atomicAdd(&sdstf[node0 * 4 + head], pd0[hl]);
            }
            if (node1 < N_NODES) {
                atomicAdd(&ssrcf[node1 * 4 + head], ps1[hl]);
                atomicAdd(&sdstf[node1 * 4 + head], pd1[hl]);
            }
        }
    }
}

// ---------------- 5. edge scatter: ex + CSR placement ------------------------
// Softmax is shift-invariant and e = tanh(.)*w in (-1,1) is bounded, so the
// reference's segment_max subtraction is mathematically a no-op.
__global__ __launch_bounds__(256) void scatter_kernel(const int* __restrict__ idx,
                                                      const float* __restrict__ wts) {
    int e = blockIdx.x * blockDim.x + threadIdx.x;
    if (e >= N_EDGES) return;
    int2 p = reinterpret_cast<const int2*>(idx)[e];
    int s = p.x, d = p.y;
    float w = wts[e];
    float4 a = g_ssrc[s];
    float4 b = g_sdst[d];
    float4 ex;
    ex.x = __expf(tanhf(a.x + b.x) * w);
    ex.y = __expf(tanhf(a.y + b.y) * w);
    ex.z = __expf(tanhf(a.z + b.z) * w);
    ex.w = __expf(tanhf(a.w + b.w) * w);
    int pos = atomicAdd(&g_cursor[d], 1);
    g_csr_ex[pos]  = ex;
    g_csr_src[pos] = s;
}

// ---------------- 6. single-pass aggregation + fused GELU (warp per dst) -----
// out = (sum_e ex_e * h_src) / (sum_e ex_e)  — denom fused into gather loop.
__global__ __launch_bounds__(256) void aggregate_kernel(float* __restrict__ out) {
    int d = (blockIdx.x * blockDim.x + threadIdx.x) >> 5;
    if (d >= N_NODES) return;
    int lane = threadIdx.x & 31;
    int h2 = lane >> 3;                 // head owning my out cols

    int start = g_start[d];
    int end   = g_start[d + 1];

    const float* exf = reinterpret_cast<const float*>(g_csr_ex);
    const uint2* hh2 = reinterpret_cast<const uint2*>(g_hh);

    float dsum = 0.f;
    float4 acc = make_float4(0.f, 0.f, 0.f, 0.f);
#pragma unroll 4
    for (int e = start; e < end; e++) {
        int src = __ldg(&g_csr_src[e]);          // warp-uniform broadcast
        float exv = __ldg(&exf[e * 4 + h2]);
        uint2 raw = __ldg(&hh2[src * 32 + lane]);
        dsum += exv;
        float2 f01 = unpack_h2(raw.x);
        float2 f23 = unpack_h2(raw.y);
        acc.x += exv * f01.x; acc.y += exv * f01.y;
        acc.z += exv * f23.x; acc.w += exv * f23.y;
    }
    float inv = (end > start) ? 1.f / dsum : 0.f;   // deg==0 -> out 0 (= ref)

    const float r = 0.70710678118654752f;
    float4 v;
    acc.x *= inv; acc.y *= inv; acc.z *= inv; acc.w *= inv;
    v.x = 0.5f * acc.x * (1.f + erff(acc.x * r));
    v.y = 0.5f * acc.y * (1.f + erff(acc.y * r));
    v.z = 0.5f * acc.z * (1.f + erff(acc.z * r));
    v.w = 0.5f * acc.w * (1.f + erff(acc.w * r));
    reinterpret_cast<float4*>(out)[d * 32 + lane] = v;
}

// ---------------- launch -----------------------------------------------------
extern "C" void kernel_launch(void* const* d_in, const int* in_sizes, int n_in,
                              void* d_out, int out_size) {
    const float* x     = (const float*)d_in[0];
    const int*   idx   = (const int*)d_in[1];     // int64 stored as int32 pairs
    const float* wts   = (const float*)d_in[2];
    const float* W     = (const float*)d_in[3];
    const float* a_src = (const float*)d_in[4];
    const float* a_dst = (const float*)d_in[5];
    float* out = (float*)d_out;

    zero_kernel<<<SCAN_NBLK, SCAN_BLK>>>();                               // 1
    count_kernel<<<(N_EDGES + 255) / 256, 256>>>(idx);                    // 2
    scan_blocks_kernel<<<SCAN_NBLK, SCAN_BLK>>>();                        // 3
    gemm_fused_kernel<<<(N_NODES + TILE_M - 1) / TILE_M, 256>>>(
        x, W, a_src, a_dst);                                              // 4 <- profiled
    scan_tops_kernel<<<1, 64>>>();                                        // 5
    scan_apply_kernel<<<SCAN_NBLK, SCAN_BLK>>>();                         // 6
    scatter_kernel<<<(N_EDGES + 255) / 256, 256>>>(idx, wts);             // 7
    aggregate_kernel<<<(N_NODES * 32 + 255) / 256, 256>>>(out);           // 8
}

// round 14
// speedup vs baseline: 1.0860x; 1.0551x over previous
#include <cuda_runtime.h>
#include <cuda_fp16.h>
#include <cuda_bf16.h>
#include <cstdint>

constexpr int N_NODES = 50000;
constexpr int N_EDGES = 1600000;
constexpr int IN_DIM  = 256;
constexpr int HD      = 128;   // HEADS * OUT_DIM

constexpr int SCAN_BLK  = 1024;
constexpr int SCAN_NBLK = (N_NODES + SCAN_BLK - 1) / SCAN_BLK;   // 49

constexpr int TILE_M = 64;                 // 2 CTAs/SM
constexpr int KC     = 32;                 // bf16 K-chunk
constexpr int KPAD   = 40;                 // smem row stride (conflict-free)
constexpr int NCH    = IN_DIM / KC;        // 8 chunks

// ---------------- scratch (static device globals) ----------------------------
__device__ uint4  g_hh[N_NODES * (HD / 8)];  // h fp16 packed (12.8 MB)
__device__ float4 g_ssrc[N_NODES];           // per-node src scores (atomic-built)
__device__ float4 g_sdst[N_NODES];
__device__ float4 g_csr_ex[N_EDGES];
__device__ int    g_csr_src[N_EDGES];
__device__ int    g_count[N_NODES];
__device__ int    g_start[N_NODES + 1];
__device__ int    g_cursor[N_NODES];
__device__ int    g_blocksum[SCAN_NBLK];

// ---------------- helpers ----------------------------------------------------
__device__ __forceinline__ unsigned pack_h2(float a, float b) {   // fp16 pair
    __half2 h = __float22half2_rn(make_float2(a, b));
    return *reinterpret_cast<unsigned*>(&h);
}
__device__ __forceinline__ float2 unpack_h2(unsigned u) {
    __half2 h = *reinterpret_cast<__half2*>(&u);
    return __half22float2(h);
}
__device__ __forceinline__ unsigned pack_bf2(__nv_bfloat16 a, __nv_bfloat16 b) {
    __nv_bfloat162 t = __halves2bfloat162(a, b);
    return *reinterpret_cast<unsigned*>(&t);
}
__device__ __forceinline__ uint32_t ld2(const uint16_t* p) {
    return *reinterpret_cast<const uint32_t*>(p);
}
// HMMA bf16: m16n8k16, row.col, fp32 accumulate (baseline PTX, sm_80+)
__device__ __forceinline__ void mma16816(float* d, const uint32_t* a,
                                         uint32_t b0, uint32_t b1) {
    asm volatile(
        "mma.sync.aligned.m16n8k16.row.col.f32.bf16.bf16.f32 "
        "{%0,%1,%2,%3}, {%4,%5,%6,%7}, {%8,%9}, {%0,%1,%2,%3};"
        : "+f"(d[0]), "+f"(d[1]), "+f"(d[2]), "+f"(d[3])
        : "r"(a[0]), "r"(a[1]), "r"(a[2]), "r"(a[3]), "r"(b0), "r"(b1));
}
// split fp32 -> (hi, lo) bf16 pair packs for 4 consecutive values
__device__ __forceinline__ void split4(float4 v, uint2& hi, uint2& lo) {
    __nv_bfloat16 h0 = __float2bfloat16_rn(v.x);
    __nv_bfloat16 h1 = __float2bfloat16_rn(v.y);
    __nv_bfloat16 h2 = __float2bfloat16_rn(v.z);
    __nv_bfloat16 h3 = __float2bfloat16_rn(v.w);
    hi = make_uint2(pack_bf2(h0, h1), pack_bf2(h2, h3));
    lo = make_uint2(pack_bf2(__float2bfloat16_rn(v.x - __bfloat162float(h0)),
                             __float2bfloat16_rn(v.y - __bfloat162float(h1))),
                    pack_bf2(__float2bfloat16_rn(v.z - __bfloat162float(h2)),
                             __float2bfloat16_rn(v.w - __bfloat162float(h3))));
}

// ---------------- 0. zero counters + score accumulators ----------------------
__global__ __launch_bounds__(SCAN_BLK) void zero_kernel() {
    int n = blockIdx.x * SCAN_BLK + threadIdx.x;
    if (n < N_NODES) {
        g_count[n] = 0;
        g_ssrc[n] = make_float4(0.f, 0.f, 0.f, 0.f);
        g_sdst[n] = make_float4(0.f, 0.f, 0.f, 0.f);
    }
}

// ---------------- 1. in-degree histogram -------------------------------------
__global__ __launch_bounds__(256) void count_kernel(const int* __restrict__ idx) {
    int e = blockIdx.x * blockDim.x + threadIdx.x;
    if (e >= N_EDGES) return;
    int2 p = reinterpret_cast<const int2*>(idx)[e];
    atomicAdd(&g_count[p.y], 1);
}

// ---------------- 2. hierarchical prefix sum ---------------------------------
__global__ __launch_bounds__(SCAN_BLK) void scan_blocks_kernel() {
    __shared__ int sh[SCAN_BLK];
    int tid = threadIdx.x;
    int n = blockIdx.x * SCAN_BLK + tid;
    int v = (n < N_NODES) ? g_count[n] : 0;
    sh[tid] = v;
    __syncthreads();
#pragma unroll
    for (int off = 1; off < SCAN_BLK; off <<= 1) {
        int t = (tid >= off) ? sh[tid - off] : 0;
        __syncthreads();
        sh[tid] += t;
        __syncthreads();
    }
    if (n < N_NODES) g_start[n] = sh[tid] - v;
    if (tid == SCAN_BLK - 1) g_blocksum[blockIdx.x] = sh[tid];
}
__global__ __launch_bounds__(64) void scan_tops_kernel() {
    __shared__ int sh[64];
    int tid = threadIdx.x;
    int v = (tid < SCAN_NBLK) ? g_blocksum[tid] : 0;
    sh[tid] = v;
    __syncthreads();
#pragma unroll
    for (int off = 1; off < 64; off <<= 1) {
        int t = (tid >= off) ? sh[tid - off] : 0;
        __syncthreads();
        sh[tid] += t;
        __syncthreads();
    }
    if (tid < SCAN_NBLK) g_blocksum[tid] = sh[tid] - v;
}
__global__ __launch_bounds__(SCAN_BLK) void scan_apply_kernel() {
    int n = blockIdx.x * SCAN_BLK + threadIdx.x;
    if (n >= N_NODES) return;
    int s = g_start[n] + g_blocksum[blockIdx.x];
    g_start[n]  = s;
    g_cursor[n] = s;
    if (n == 0) g_start[N_NODES] = N_EDGES;
}

// ---------------- 3. pipelined HMMA GEMM + fused scores ----------------------
// h = x_hi*W_hi + x_hi*W_lo + x_lo*W_hi (fp32 acc). Epilogue: packed fp16 h
// AND per-node attention scores s_src/s_dst via fp32 atomics.
// Merged product loop: each WH fragment loaded once per k-step.
__global__ __launch_bounds__(256, 2) void gemm_fused_kernel(
        const float* __restrict__ x, const float* __restrict__ W,
        const float* __restrict__ a_src, const float* __restrict__ a_dst) {
    __shared__ uint16_t XH[2][TILE_M][KPAD];
    __shared__ uint16_t XL[2][TILE_M][KPAD];
    __shared__ uint16_t WH[2][HD][KPAD];
    __shared__ uint16_t WL[2][HD][KPAD];

    const int tid  = threadIdx.x;
    const int lane = tid & 31;
    const int wid  = tid >> 5;
    const int warp_m = wid >> 1;        // 0..3 -> rows 16*warp_m
    const int warp_n = wid & 1;         // 0..1 -> cols 64*warp_n
    const int mBase = blockIdx.x * TILE_M;

    const int qr = lane >> 2;           // 0..7
    const int qc = (lane & 3) * 2;      // 0,2,4,6

    const int xr0 = tid >> 3,         xc0 = (tid & 7) * 4;
    const int xr1 = (256 + tid) >> 3, xc1 = ((256 + tid) & 7) * 4;

    float d[8][4];
#pragma unroll
    for (int j = 0; j < 8; j++)
#pragma unroll
        for (int t = 0; t < 4; t++) d[j][t] = 0.f;

    float4 xv[2], wv[4];
    const bool xok0 = (mBase + xr0 < N_NODES);
    const bool xok1 = (mBase + xr1 < N_NODES);
    // prologue: chunk 0
    xv[0] = xok0 ? *reinterpret_cast<const float4*>(&x[(long)(mBase + xr0) * IN_DIM + xc0])
                 : make_float4(0.f, 0.f, 0.f, 0.f);
    xv[1] = xok1 ? *reinterpret_cast<const float4*>(&x[(long)(mBase + xr1) * IN_DIM + xc1])
                 : make_float4(0.f, 0.f, 0.f, 0.f);
#pragma unroll
    for (int q = 0; q < 4; q++) {
        int i = q * 256 + tid;
        wv[q] = *reinterpret_cast<const float4*>(&W[(long)(i >> 3) * IN_DIM + (i & 7) * 4]);
    }

    for (int c = 0; c < NCH; c++) {
        const int b = c & 1;
        // ---- convert prefetched regs -> smem buffer b ----
        {
            uint2 hi, lo;
            split4(xv[0], hi, lo);
            *reinterpret_cast<uint2*>(&XH[b][xr0][xc0]) = hi;
            *reinterpret_cast<uint2*>(&XL[b][xr0][xc0]) = lo;
            split4(xv[1], hi, lo);
            *reinterpret_cast<uint2*>(&XH[b][xr1][xc1]) = hi;
            *reinterpret_cast<uint2*>(&XL[b][xr1][xc1]) = lo;
#pragma unroll
            for (int q = 0; q < 4; q++) {
                int i = q * 256 + tid;
                split4(wv[q], hi, lo);
                *reinterpret_cast<uint2*>(&WH[b][i >> 3][(i & 7) * 4]) = hi;
                *reinterpret_cast<uint2*>(&WL[b][i >> 3][(i & 7) * 4]) = lo;
            }
        }
        __syncthreads();

        // ---- issue LDGs for chunk c+1 (overlap with MMA below) ----
        if (c + 1 < NCH) {
            const int k0 = (c + 1) * KC;
            xv[0] = xok0 ? *reinterpret_cast<const float4*>(&x[(long)(mBase + xr0) * IN_DIM + k0 + xc0])
                         : make_float4(0.f, 0.f, 0.f, 0.f);
            xv[1] = xok1 ? *reinterpret_cast<const float4*>(&x[(long)(mBase + xr1) * IN_DIM + k0 + xc1])
                         : make_float4(0.f, 0.f, 0.f, 0.f);
#pragma unroll
            for (int q = 0; q < 4; q++) {
                int i = q * 256 + tid;
                wv[q] = *reinterpret_cast<const float4*>(&W[(long)(i >> 3) * IN_DIM + k0 + (i & 7) * 4]);
            }
        }

        // ---- MMA from buffer b: merged 3-product loop ----
#pragma unroll
        for (int ks = 0; ks < 2; ks++) {
            const int kb = ks * 16 + qc;
            const int r = warp_m * 16 + qr;
            uint32_t ah[4], al[4];
            ah[0] = ld2(&XH[b][r][kb]);     ah[1] = ld2(&XH[b][r + 8][kb]);
            ah[2] = ld2(&XH[b][r][kb + 8]); ah[3] = ld2(&XH[b][r + 8][kb + 8]);
            al[0] = ld2(&XL[b][r][kb]);     al[1] = ld2(&XL[b][r + 8][kb]);
            al[2] = ld2(&XL[b][r][kb + 8]); al[3] = ld2(&XL[b][r + 8][kb + 8]);
#pragma unroll
            for (int j = 0; j < 8; j++) {
                int n = warp_n * 64 + j * 8 + qr;
                uint32_t b0 = ld2(&WH[b][n][kb]), b1 = ld2(&WH[b][n][kb + 8]);
                mma16816(d[j], ah, b0, b1);
                uint32_t c0 = ld2(&WL[b][n][kb]), c1 = ld2(&WL[b][n][kb + 8]);
                mma16816(d[j], ah, c0, c1);
                mma16816(d[j], al, b0, b1);     // WH frags reused from regs
            }
        }
        // single barrier/iter: next STS hits the other buffer.
    }

    // ---- epilogue: packed fp16 h + fused attention scores ----
    unsigned* hhu = reinterpret_cast<unsigned*>(g_hh);
    float* ssrcf = reinterpret_cast<float*>(g_ssrc);
    float* sdstf = reinterpret_cast<float*>(g_sdst);

    const int node0 = mBase + warp_m * 16 + qr;
    const int node1 = node0 + 8;

    float ps0[2] = {0.f, 0.f}, pd0[2] = {0.f, 0.f};
    float ps1[2] = {0.f, 0.f}, pd1[2] = {0.f, 0.f};
#pragma unroll
    for (int j = 0; j < 8; j++) {
        int colb = warp_n * 64 + j * 8 + qc;          // even; pair stays in head
        int hl   = j >> 2;                            // 0/1 within warp's heads
        int head = warp_n * 2 + hl;
#pragma unroll
        for (int t = 0; t < 2; t++) {
            int dim = (colb + t) & 31;
            float asv = __ldg(&a_src[head * 32 + dim]);
            float adv = __ldg(&a_dst[head * 32 + dim]);
            ps0[hl] += d[j][t] * asv;     pd0[hl] += d[j][t] * adv;
            ps1[hl] += d[j][2 + t] * asv; pd1[hl] += d[j][2 + t] * adv;
        }
        if (node0 < N_NODES)
            hhu[node0 * 64 + (colb >> 1)] = pack_h2(d[j][0], d[j][1]);
        if (node1 < N_NODES)
            hhu[node1 * 64 + (colb >> 1)] = pack_h2(d[j][2], d[j][3]);
    }
    // reduce across the 4 lanes sharing (node, head): lane = qr*4 + {0..3}
#pragma unroll
    for (int hl = 0; hl < 2; hl++) {
#pragma unroll
        for (int o = 1; o <= 2; o <<= 1) {
            ps0[hl] += __shfl_xor_sync(0xffffffffu, ps0[hl], o);
            pd0[hl] += __shfl_xor_sync(0xffffffffu, pd0[hl], o);
            ps1[hl] += __shfl_xor_sync(0xffffffffu, ps1[hl], o);
            pd1[hl] += __shfl_xor_sync(0xffffffffu, pd1[hl], o);
        }
    }
    if ((lane & 3) == 0) {
#pragma unroll
        for (int hl = 0; hl < 2; hl++) {
            int head = warp_n * 2 + hl;
            if (node0 < N_NODES) {
                atomicAdd(&ssrcf[node0 * 4 + head], ps0[hl]);
                atomicAdd(&sdstf[node0 * 4 + head], pd0[hl]);
            }
            if (node1 < N_NODES) {
                atomicAdd(&ssrcf[node1 * 4 + head], ps1[hl]);
                atomicAdd(&sdstf[node1 * 4 + head], pd1[hl]);
            }
        }
    }
}

// ---------------- 5. edge scatter: ex + CSR placement ------------------------
// Softmax is shift-invariant and e = tanh(.)*w in (-1,1) is bounded, so the
// reference's segment_max subtraction is mathematically a no-op.
__global__ __launch_bounds__(256) void scatter_kernel(const int* __restrict__ idx,
                                                      const float* __restrict__ wts) {
    int e = blockIdx.x * blockDim.x + threadIdx.x;
    if (e >= N_EDGES) return;
    int2 p = reinterpret_cast<const int2*>(idx)[e];
    int s = p.x, d = p.y;
    float w = wts[e];
    float4 a = g_ssrc[s];
    float4 b = g_sdst[d];
    float4 ex;
    ex.x = __expf(tanhf(a.x + b.x) * w);
    ex.y = __expf(tanhf(a.y + b.y) * w);
    ex.z = __expf(tanhf(a.z + b.z) * w);
    ex.w = __expf(tanhf(a.w + b.w) * w);
    int pos = atomicAdd(&g_cursor[d], 1);
    g_csr_ex[pos]  = ex;
    g_csr_src[pos] = s;
}

// ---------------- 6. single-pass aggregation + fused GELU (warp per dst) -----
// out = (sum_e ex_e * h_src) / (sum_e ex_e)  — denom fused into gather loop.
__global__ __launch_bounds__(256) void aggregate_kernel(float* __restrict__ out) {
    int d = (blockIdx.x * blockDim.x + threadIdx.x) >> 5;
    if (d >= N_NODES) return;
    int lane = threadIdx.x & 31;
    int h2 = lane >> 3;                 // head owning my out cols

    int start = g_start[d];
    int end   = g_start[d + 1];

    const float* exf = reinterpret_cast<const float*>(g_csr_ex);
    const uint2* hh2 = reinterpret_cast<const uint2*>(g_hh);

    float dsum = 0.f;
    float4 acc = make_float4(0.f, 0.f, 0.f, 0.f);
#pragma unroll 4
    for (int e = start; e < end; e++) {
        int src = __ldg(&g_csr_src[e]);          // warp-uniform broadcast
        float exv = __ldg(&exf[e * 4 + h2]);
        uint2 raw = __ldg(&hh2[src * 32 + lane]);
        dsum += exv;
        float2 f01 = unpack_h2(raw.x);
        float2 f23 = unpack_h2(raw.y);
        acc.x += exv * f01.x; acc.y += exv * f01.y;
        acc.z += exv * f23.x; acc.w += exv * f23.y;
    }
    float inv = (end > start) ? 1.f / dsum : 0.f;   // deg==0 -> out 0 (= ref)

    const float r = 0.70710678118654752f;
    float4 v;
    acc.x *= inv; acc.y *= inv; acc.z *= inv; acc.w *= inv;
    v.x = 0.5f * acc.x * (1.f + erff(acc.x * r));
    v.y = 0.5f * acc.y * (1.f + erff(acc.y * r));
    v.z = 0.5f * acc.z * (1.f + erff(acc.z * r));
    v.w = 0.5f * acc.w * (1.f + erff(acc.w * r));
    reinterpret_cast<float4*>(out)[d * 32 + lane] = v;
}

// ---------------- launch: fork-join graph ------------------------------------
//   zero ─┬─ gemm ─────────────────┬─ scatter ─ aggregate     (stream 0)
//         └─ count → scans ─(join)─┘                           (stream s2)
// The count/scan chain (~23us) hides fully under the 46us GEMM.
extern "C" void kernel_launch(void* const* d_in, const int* in_sizes, int n_in,
                              void* d_out, int out_size) {
    const float* x     = (const float*)d_in[0];
    const int*   idx   = (const int*)d_in[1];     // int64 stored as int32 pairs
    const float* wts   = (const float*)d_in[2];
    const float* W     = (const float*)d_in[3];
    const float* a_src = (const float*)d_in[4];
    const float* a_dst = (const float*)d_in[5];
    float* out = (float*)d_out;

    // one-time plumbing (streams/events are infrastructure, not device memory;
    // the WORK issued per call is identical every time)
    static cudaStream_t s2 = nullptr;
    static cudaEvent_t evFork = nullptr, evJoin = nullptr;
    if (s2 == nullptr) {
        cudaStreamCreateWithFlags(&s2, cudaStreamNonBlocking);
        cudaEventCreateWithFlags(&evFork, cudaEventDisableTiming);
        cudaEventCreateWithFlags(&evJoin, cudaEventDisableTiming);
    }

    zero_kernel<<<SCAN_NBLK, SCAN_BLK>>>();
    cudaEventRecord(evFork, 0);
    cudaStreamWaitEvent(s2, evFork, 0);

    // side stream: CSR offsets (independent of GEMM)
    count_kernel<<<(N_EDGES + 255) / 256, 256, 0, s2>>>(idx);
    scan_blocks_kernel<<<SCAN_NBLK, SCAN_BLK, 0, s2>>>();
    scan_tops_kernel<<<1, 64, 0, s2>>>();
    scan_apply_kernel<<<SCAN_NBLK, SCAN_BLK, 0, s2>>>();
    cudaEventRecord(evJoin, s2);

    // main stream: GEMM overlaps the side chain
    gemm_fused_kernel<<<(N_NODES + TILE_M - 1) / TILE_M, 256>>>(x, W, a_src, a_dst);

    cudaStreamWaitEvent(0, evJoin, 0);
    scatter_kernel<<<(N_EDGES + 255) / 256, 256>>>(idx, wts);
    aggregate_kernel<<<(N_NODES * 32 + 255) / 256, 256>>>(out);
}